// round 8
// baseline (speedup 1.0000x reference)
#include <cuda_runtime.h>

// Problem constants
#define QQ 30
#define KK 1024
#define DD 128
#define BB 16
#define TT 2048
#define NTOK (BB*TT)          // 32768 tokens
#define OUT_ELEMS (NTOK*DD)   // 4194304 quantized elements

// Tiling
#define TM 128                // tokens per CTA
#define KC 128                // codes per chunk
#define NCH (KK/KC)           // 8 chunks
#define NT 256                // threads per CTA

// Scratch (no cudaMalloc allowed): transposed codebooks [q][d][k] + code norms
__device__ float g_ct[(size_t)QQ*DD*KK];   // 15.7 MB
__device__ float g_cn[QQ*KK];              // 120 KB

// ---------------------------------------------------------------------------
// Emulation of XLA:CPU sharded-vector square-sum reduce of a 128-wide row:
// two <4 x float> accumulator shards (8 elems/iter, contiguous):
//   shard0 lane l += x^2[8j+l],  shard1 lane l += x^2[8j+4+l],  j = 0..15.
// Epilogue (THE single change this round): shards combined lanewise, then
// elements extracted and added SEQUENTIALLY left-to-right:
//   v = s0 + s1 (lanewise);  out = ((v0 + v1) + v2) + v3
// (previous round used the FADDP-adjacent pairing ((v0+v1)+(v2+v3)) -- that
// world is falsified). FMA kept (R5 vs R6 proved fma/mul+add equivalence).
// ---------------------------------------------------------------------------
#define RED_ACC(a0, a1, v0, v1, v2, v3, v4, v5, v6, v7)                  \
    do {                                                                 \
        a0[0] = __fmaf_rn((v0), (v0), a0[0]);                            \
        a0[1] = __fmaf_rn((v1), (v1), a0[1]);                            \
        a0[2] = __fmaf_rn((v2), (v2), a0[2]);                            \
        a0[3] = __fmaf_rn((v3), (v3), a0[3]);                            \
        a1[0] = __fmaf_rn((v4), (v4), a1[0]);                            \
        a1[1] = __fmaf_rn((v5), (v5), a1[1]);                            \
        a1[2] = __fmaf_rn((v6), (v6), a1[2]);                            \
        a1[3] = __fmaf_rn((v7), (v7), a1[3]);                            \
    } while (0)

__device__ __forceinline__ float red_combine(const float a0[4], const float a1[4])
{
    float v0 = __fadd_rn(a0[0], a1[0]);
    float v1 = __fadd_rn(a0[1], a1[1]);
    float v2 = __fadd_rn(a0[2], a1[2]);
    float v3 = __fadd_rn(a0[3], a1[3]);
    // sequential left-assoc extraction (sharded-vector emitter epilogue)
    return __fadd_rn(__fadd_rn(__fadd_rn(v0, v1), v2), v3);
}

// ---------------------------------------------------------------------------
// Prep A: transpose codebooks to [q][d][k]; zero loss slot. Warp per code row.
// ---------------------------------------------------------------------------
__global__ void rvq_prep_kernel(const float* __restrict__ cb,
                                float* __restrict__ out, int write_loss)
{
    if (write_loss && blockIdx.x == 0 && threadIdx.x == 0)
        out[OUT_ELEMS] = 0.0f;

    int gw   = blockIdx.x * 8 + (threadIdx.x >> 5);   // global code row (q*KK+k)
    int lane = threadIdx.x & 31;
    if (gw >= QQ * KK) return;

    int q = gw >> 10;
    int k = gw & (KK - 1);

    float4 v = __ldg(((const float4*)cb) + (size_t)gw * (DD/4) + lane);

    float* base = g_ct + (size_t)q * DD * KK + k;
    int d0 = lane * 4;
    base[(size_t)(d0+0)*KK] = v.x;
    base[(size_t)(d0+1)*KK] = v.y;
    base[(size_t)(d0+2)*KK] = v.z;
    base[(size_t)(d0+3)*KK] = v.w;
}

// ---------------------------------------------------------------------------
// Prep B: ||c||^2 with the sharded-vector association. Thread per code row.
// ---------------------------------------------------------------------------
__global__ void rvq_norm_kernel(const float* __restrict__ cb)
{
    int gw = blockIdx.x * blockDim.x + threadIdx.x;   // code row (q*KK+k)
    if (gw >= QQ * KK) return;
    const float4* row = ((const float4*)cb) + (size_t)gw * (DD/4);
    float a0[4] = {0.f,0.f,0.f,0.f}, a1[4] = {0.f,0.f,0.f,0.f};
    #pragma unroll
    for (int j = 0; j < 16; j++) {
        float4 A = __ldg(row + 2*j);
        float4 B = __ldg(row + 2*j + 1);
        RED_ACC(a0, a1, A.x, A.y, A.z, A.w, B.x, B.y, B.z, B.w);
    }
    g_cn[gw] = red_combine(a0, a1);
}

// ---------------------------------------------------------------------------
// Main kernel. Per-CTA 128-token tile, residuals SMEM-resident for 30 stages.
// Stage: fp32 min-GEMM (ascending-d single FMA chain per output = Eigen NEON
// gebp) -> score fl(fl(r2 - fl(2e)) + c2) -> first-min argmin -> residual
// update + next-stage r2 (sharded-vector association) + loss.
// ---------------------------------------------------------------------------
__global__ __launch_bounds__(NT, 1)
void rvq_kernel(const float* __restrict__ x,
                const float* __restrict__ cb,
                float* __restrict__ out, int write_loss)
{
    extern __shared__ char smraw[];
    float*  rs    = (float*)smraw;                   // residuals [DD][TM]
    float*  cs    = rs + DD*TM;                      // code chunk [DD][KC]
    float*  r2_s  = cs + DD*KC;                      // [TM] ||r||^2 per token
    int*    idx_s = (int*)(r2_s + TM);               // [TM] winner per token
    double* red   = (double*)(idx_s + TM);           // [8] loss partials

    const int tid = threadIdx.x;
    const int tx  = tid & 15;      // code-thread column (16)
    const int ty  = tid >> 4;      // token-thread row   (16)

    const int blk = blockIdx.x;
    const int b   = blk >> 4;            // TT/TM = 16 tiles per batch row
    const int t0  = (blk & 15) * TM;
    const float* xb = x + (size_t)b * DD * TT + t0;

    float4* rs4 = (float4*)rs;
    float4* cs4 = (float4*)cs;

    // Load initial residual r0 = x (transposed into [d][token]); coalesced.
    for (int i = tid; i < DD*TM/4; i += NT) {
        int tok4 = i & 31, d = i >> 5;
        float4 v = __ldg((const float4*)(xb + (size_t)d * TT) + tok4);
        rs4[d * (TM/4) + tok4] = v;
    }
    __syncthreads();

    // Initial r2 with the sharded-vector association.
    if (tid < TM) {
        float a0[4] = {0.f,0.f,0.f,0.f}, a1[4] = {0.f,0.f,0.f,0.f};
        #pragma unroll
        for (int j = 0; j < 16; j++) {
            int d = 8*j;
            RED_ACC(a0, a1,
                    rs[(d+0)*TM + tid], rs[(d+1)*TM + tid],
                    rs[(d+2)*TM + tid], rs[(d+3)*TM + tid],
                    rs[(d+4)*TM + tid], rs[(d+5)*TM + tid],
                    rs[(d+6)*TM + tid], rs[(d+7)*TM + tid]);
        }
        r2_s[tid] = red_combine(a0, a1);
    }

    double lossAcc = 0.0;

    for (int q = 0; q < QQ; q++) {
        // Running best per owned token row: key = (sortable bits << 32) | idx
        unsigned long long best[8];
        #pragma unroll
        for (int r = 0; r < 8; r++) best[r] = 0xFFFFFFFFFFFFFFFFull;

        const float* ctq = g_ct + (size_t)q * DD * KK;
        const float* cnq = g_cn + q * KK;

        for (int ch = 0; ch < NCH; ch++) {
            __syncthreads();   // rs/r2 writes (prev) & cs reads (prev chunk) done
            for (int i = tid; i < DD*KC/4; i += NT) {
                int k4 = i & 31, d = i >> 5;
                float4 v = __ldg((const float4*)(ctq + (size_t)d * KK + ch*KC) + k4);
                cs4[d * (KC/4) + k4] = v;
            }
            __syncthreads();

            // 8x8 register tile; each acc is a single FMA chain, d ascending.
            float acc[8][8];
            #pragma unroll
            for (int r = 0; r < 8; r++)
                #pragma unroll
                for (int c = 0; c < 8; c++) acc[r][c] = 0.0f;

            #pragma unroll 8
            for (int d = 0; d < DD; d++) {
                float4 a0 = rs4[d * (TM/4) + ty*2];
                float4 a1 = rs4[d * (TM/4) + ty*2 + 1];
                float4 b0 = cs4[d * (KC/4) + tx*2];
                float4 b1 = cs4[d * (KC/4) + tx*2 + 1];
                float ar[8] = {a0.x,a0.y,a0.z,a0.w,a1.x,a1.y,a1.z,a1.w};
                float bc[8] = {b0.x,b0.y,b0.z,b0.w,b1.x,b1.y,b1.z,b1.w};
                #pragma unroll
                for (int r = 0; r < 8; r++)
                    #pragma unroll
                    for (int c = 0; c < 8; c++)
                        acc[r][c] = __fmaf_rn(ar[r], bc[c], acc[r][c]);
            }

            // score = fl(fl(r2 - fl(2*e)) + c2); fl(2e) is exact, so this is
            // also bitwise what a contracted fnmsub+fadd emits.
            const int kg0 = ch*KC + tx*8;
            float cn[8];
            #pragma unroll
            for (int c = 0; c < 8; c++) cn[c] = __ldg(cnq + kg0 + c);

            #pragma unroll
            for (int r = 0; r < 8; r++) {
                float r2v = r2_s[ty*8 + r];           // broadcast LDS
                #pragma unroll
                for (int c = 0; c < 8; c++) {
                    float e2 = __fmul_rn(2.0f, acc[r][c]);   // exact
                    float u  = __fsub_rn(r2v, e2);
                    float s  = __fadd_rn(u, cn[c]);
                    unsigned uu = __float_as_uint(s);
                    uu = (uu & 0x80000000u) ? ~uu : (uu | 0x80000000u);
                    unsigned long long key =
                        ((unsigned long long)uu << 32) | (unsigned)(kg0 + c);
                    if (key < best[r]) best[r] = key;   // ties -> lowest index
                }
            }
        }

        // Reduce over the 16 tx lanes (butterfly within half-warp)
        #pragma unroll
        for (int r = 0; r < 8; r++) {
            unsigned long long kmin = best[r];
            #pragma unroll
            for (int off = 8; off > 0; off >>= 1) {
                unsigned long long o = __shfl_xor_sync(0xffffffffu, kmin, off);
                if (o < kmin) kmin = o;
            }
            if (tx == 0) idx_s[ty*8 + r] = (int)(kmin & 0xFFFFFFFFull);
        }
        __syncthreads();   // idx visible; all GEMM reads of rs/r2 done

        // Residual update (one thread per token, d ascending) + next r2 with
        // the sharded-vector association + loss.
        if (tid < TM) {
            const int tok = tid;
            const int widx = idx_s[tok];
            const float4* crow =
                (const float4*)(cb + ((size_t)q * KK + widx) * DD);
            float a0[4] = {0.f,0.f,0.f,0.f}, a1[4] = {0.f,0.f,0.f,0.f};
            float lsum = 0.0f;
            #pragma unroll
            for (int j = 0; j < 16; j++) {
                float4 cA = __ldg(crow + 2*j);
                float4 cB = __ldg(crow + 2*j + 1);
                int d = 8*j;
                float n0 = __fsub_rn(rs[(d+0)*TM + tok], cA.x);
                float n1 = __fsub_rn(rs[(d+1)*TM + tok], cA.y);
                float n2 = __fsub_rn(rs[(d+2)*TM + tok], cA.z);
                float n3 = __fsub_rn(rs[(d+3)*TM + tok], cA.w);
                float n4 = __fsub_rn(rs[(d+4)*TM + tok], cB.x);
                float n5 = __fsub_rn(rs[(d+5)*TM + tok], cB.y);
                float n6 = __fsub_rn(rs[(d+6)*TM + tok], cB.z);
                float n7 = __fsub_rn(rs[(d+7)*TM + tok], cB.w);
                rs[(d+0)*TM + tok] = n0;
                rs[(d+1)*TM + tok] = n1;
                rs[(d+2)*TM + tok] = n2;
                rs[(d+3)*TM + tok] = n3;
                rs[(d+4)*TM + tok] = n4;
                rs[(d+5)*TM + tok] = n5;
                rs[(d+6)*TM + tok] = n6;
                rs[(d+7)*TM + tok] = n7;
                RED_ACC(a0, a1, n0, n1, n2, n3, n4, n5, n6, n7);
                lsum += n0*n0 + n1*n1 + n2*n2 + n3*n3
                      + n4*n4 + n5*n5 + n6*n6 + n7*n7;
            }
            r2_s[tok] = red_combine(a0, a1);
            lossAcc += (double)lsum;
        }
        // next iteration's leading __syncthreads orders rs/r2 writes
    }
    __syncthreads();

    // quantized = x - r_final (telescoped), layout [B,D,T]
    for (int i = tid; i < DD*TM/4; i += NT) {
        int tok4 = i & 31, d = i >> 5;
        float4 xv = __ldg((const float4*)(xb + (size_t)d * TT) + tok4);
        float4 rv = rs4[d * (TM/4) + tok4];
        float4 o;
        o.x = xv.x - rv.x; o.y = xv.y - rv.y;
        o.z = xv.z - rv.z; o.w = xv.w - rv.w;
        ((float4*)(out + ((size_t)b * DD + d) * TT + t0))[tok4] = o;
    }

    // total_loss = sum_q mean(r_{q+1}^2)
    if (write_loss) {
        #pragma unroll
        for (int off = 16; off > 0; off >>= 1)
            lossAcc += __shfl_xor_sync(0xffffffffu, lossAcc, off);
        if ((tid & 31) == 0) red[tid >> 5] = lossAcc;
        __syncthreads();
        if (tid == 0) {
            double s = 0.0;
            #pragma unroll
            for (int w = 0; w < 8; w++) s += red[w];
            atomicAdd(out + OUT_ELEMS, (float)(s * (1.0 / (double)OUT_ELEMS)));
        }
    }
}

// ---------------------------------------------------------------------------
extern "C" void kernel_launch(void* const* d_in, const int* in_sizes, int n_in,
                              void* d_out, int out_size)
{
    const float* x  = (const float*)d_in[0];   // [16,128,2048] fp32
    const float* cb = (const float*)d_in[1];   // [30,1024,128] fp32
    float* out = (float*)d_out;                // [16,128,2048] + loss scalar
    int write_loss = (out_size > OUT_ELEMS) ? 1 : 0;

    rvq_prep_kernel<<<(QQ*KK)/8, 256>>>(cb, out, write_loss);
    rvq_norm_kernel<<<(QQ*KK + 255)/256, 256>>>(cb);

    size_t smem = (size_t)(DD*TM + DD*KC + TM) * sizeof(float)
                + (size_t)TM * sizeof(int)
                + 8 * sizeof(double);
    cudaFuncSetAttribute(rvq_kernel,
                         cudaFuncAttributeMaxDynamicSharedMemorySize, (int)smem);
    rvq_kernel<<<NTOK/TM, NT, smem>>>(x, cb, out, write_loss);
}